// round 8
// baseline (speedup 1.0000x reference)
#include <cuda_runtime.h>
#include <math.h>

// ---------------- problem constants ----------------
#define M_SAMP 102400
#define NCOIL  12
#define NG     640          // oversampled grid
#define NH     320          // image size
#define NP     645          // padded grid dim (halo: -2..642)

#define PI_D 3.14159265358979323846
#define BETA_D (PI_D * 4.4102154142094819)   /* pi*sqrt(19.45) */

// padded smem indexing to avoid strided bank conflicts
#define PHYS(i) ((i) + ((i) >> 2))

// ---------------- static device scratch ----------------
__device__ float2 g_final[NP * NP * NCOIL];  // padded final grid [k2+2][kr+2][c] (39.9MB)
__device__ float2 g_mid  [NCOIL * NG * NG];  // after pass A: [c][k2][r]
__device__ float2 g_T128[96];                // W128^k
__device__ float2 g_T640[512];               // W640^e
__device__ float  g_S[NH];                   // apod reciprocal * 1/sqrt(640)

__constant__ float2 c_W5[5] = {
    { 1.0f,                 0.0f                },
    { 0.30901699437494745f,-0.9510565162951535f },
    {-0.80901699437494745f,-0.5877852522924731f },
    {-0.80901699437494745f, 0.5877852522924731f },
    { 0.30901699437494745f, 0.9510565162951535f }
};

__device__ __forceinline__ float2 cmul(float2 a, float2 b) {
    return make_float2(a.x*b.x - a.y*b.y, a.x*b.y + a.y*b.x);
}

// ---------------- kernel 1: tables ----------------
__global__ void prep_kernel() {
    int t = threadIdx.x;   // 640 threads
    if (t < 96) {
        double a = -2.0 * PI_D * (double)t / 128.0;
        g_T128[t] = make_float2((float)cos(a), (float)sin(a));
    }
    if (t < 512) {
        double a = -2.0 * PI_D * (double)t / 640.0;
        g_T640[t] = make_float2((float)cos(a), (float)sin(a));
    }
    if (t < NH) {
        float n = (float)t - 160.0f;
        float acc = 0.0f;
        #pragma unroll
        for (int js = -6; js <= 6; ++js) {
            float m = fabsf((float)js) * (1.0f/3.0f);
            float kv = 0.0f;
            if (m <= 1.0f) {
                float arg = fmaxf(1.0f - m*m, 0.0f);
                kv = cyl_bessel_i0f((float)BETA_D * sqrtf(arg)) * (1.0f/6.0f);
            }
            acc += kv * cosf(2.0f * (float)PI_D * (float)js * n / 640.0f);
        }
        g_S[t] = 1.0f / acc * 0.039528470752104741f;   // 1/sqrt(640)
    }
}

// ---------------- radix-4 Stockham work item ----------------
__device__ __forceinline__ void r4_item(const float2* X, float2* Y, int w, int s) {
    int sub = w >> 5;
    int bb  = w & 31;
    int q   = bb & (s - 1);
    int ps  = bb - q;            // p*s
    int bi  = sub * 128;
    float2 x0 = X[PHYS(bi + bb)];
    float2 x1 = X[PHYS(bi + bb + 32)];
    float2 x2 = X[PHYS(bi + bb + 64)];
    float2 x3 = X[PHYS(bi + bb + 96)];
    float2 A = make_float2(x0.x + x2.x, x0.y + x2.y);
    float2 B = make_float2(x1.x + x3.x, x1.y + x3.y);
    float2 C = make_float2(x0.x - x2.x, x0.y - x2.y);
    float2 D = make_float2(x1.x - x3.x, x1.y - x3.y);
    float2 E = make_float2(D.y, -D.x);              // -i*D
    float2 w1 = g_T128[ps];
    float2 w2 = g_T128[2*ps];
    float2 w3 = g_T128[3*ps];
    int o = bi + 4*ps + q;
    Y[PHYS(o)]       = make_float2(A.x + B.x, A.y + B.y);
    Y[PHYS(o + s)]   = cmul(make_float2(C.x + E.x, C.y + E.y), w1);
    Y[PHYS(o + 2*s)] = cmul(make_float2(A.x - B.x, A.y - B.y), w2);
    Y[PHYS(o + 3*s)] = cmul(make_float2(C.x - E.x, C.y - E.y), w3);
}

// 640-pt FFT on decimated data in A; RESULT left in A (PHYS-indexed, natural order)
__device__ __forceinline__ void fft_line_stage(float2* A, float2* B, int lane) {
    float2 *X = A, *Y = B;
    #pragma unroll
    for (int st = 0; st < 3; ++st) {
        int s = 1 << (2*st);
        r4_item(X, Y, lane, s);
        if (lane < 32) r4_item(X, Y, 128 + lane, s);
        __syncthreads();
        float2* t = X; X = Y; Y = t;
    }
    // after 3 swaps X==B, Y==A: read X, write results into Y (=A)
    int l6 = lane & 63;
    float2 v[5];
    #pragma unroll
    for (int j = 0; j < 5; ++j) {
        float2 u = X[PHYS(j*128 + l6)];
        float2 w = X[PHYS(j*128 + l6 + 64)];
        float2 f = (lane < 64) ? make_float2(u.x + w.x, u.y + w.y)
                               : make_float2(u.x - w.x, u.y - w.y);
        v[j] = cmul(f, g_T640[j * lane]);
    }
    #pragma unroll
    for (int k2 = 0; k2 < 5; ++k2) {
        float2 acc = v[0];
        #pragma unroll
        for (int j = 1; j < 5; ++j) {
            float2 w5 = c_W5[(j * k2) % 5];
            acc.x += v[j].x * w5.x - v[j].y * w5.y;
            acc.y += v[j].x * w5.y + v[j].y * w5.x;
        }
        Y[PHYS(lane + 128 * k2)] = acc;
    }
}

// ---------------- pass A: fused build + column FFT, row-paired float4 store ----------------
__global__ void fftA_kernel(const float* __restrict__ imr, const float* __restrict__ imi,
                            const float* __restrict__ smr, const float* __restrict__ smi) {
    __shared__ float2 SA[2][800];
    __shared__ float2 SB[2][800];
    int tid  = threadIdx.x;
    int lane = tid & 127;
    int ln   = tid >> 7;
    int b    = blockIdx.x;                   // [0, 12*160)
    int coil = b / 160;
    int q    = b - coil * 160;
    int rr   = 2*q + ln;                     // [0,320), pair stays in one half
    int h    = (rr < 160) ? rr + 160 : rr - 160;

    float sh_ = g_S[h];
    const float* smr_c = smr + coil * (NH*NH);
    const float* smi_c = smi + coil * (NH*NH);

    #pragma unroll
    for (int j = 0; j < 5; ++j) {
        int sc = 5 * lane + j;               // shifted column index
        float2 val = make_float2(0.f, 0.f);
        int w = -1;
        if (sc < 160) w = sc + 160;
        else if (sc >= 480) w = sc - 480;
        if (w >= 0) {
            int ii = h * NH + w;
            float ir = imr[ii], ij = imi[ii];
            float sr = smr_c[ii], sj = smi_c[ii];
            float sca = sh_ * g_S[w];
            val.x = (ir*sr - ij*sj) * sca;
            val.y = (ir*sj + ij*sr) * sca;
        }
        SA[ln][PHYS(j*128 + lane)] = val;    // decimated: A[j*128+n1] = x[5*n1+j]
    }
    __syncthreads();
    fft_line_stage(SA[ln], SB[ln], lane);    // result in SA[ln]
    __syncthreads();

    // cooperative float4 store: g_mid[(coil*NG + k2)*NG + r0..r0+1]
    int rr0 = 2*q;
    int r0  = (rr0 < 160) ? rr0 : rr0 + 320;  // even
    float2* gbase = g_mid + coil * (NG*NG) + r0;
    for (int k2 = tid; k2 < NG; k2 += 256) {
        float2 a = SA[0][PHYS(k2)];
        float2 bb = SA[1][PHYS(k2)];
        *reinterpret_cast<float4*>(gbase + k2 * NG) = make_float4(a.x, a.y, bb.x, bb.y);
    }
}

// ---------------- pass B: row FFT + coil-paired store + inline halo duplication ----------------
__global__ void fftB_kernel() {
    __shared__ float2 SA[2][800];
    __shared__ float2 SB[2][800];
    int tid  = threadIdx.x;
    int lane = tid & 127;
    int ln   = tid >> 7;
    int b    = blockIdx.x;                   // [0, 640*6)
    int k2   = b / 6;
    int cp   = b - k2 * 6;
    int coil = 2*cp + ln;
    const float2* gin = g_mid + (coil * NG + k2) * NG;

    #pragma unroll
    for (int j = 0; j < 5; ++j) {
        int sc = 5 * lane + j;
        float2 val = make_float2(0.f, 0.f);
        if (sc < 160 || sc >= 480) val = __ldg(&gin[sc]);
        SA[ln][PHYS(j*128 + lane)] = val;
    }
    __syncthreads();
    fft_line_stage(SA[ln], SB[ln], lane);    // result in SA[ln]
    __syncthreads();

    // main line store (xp = kr+2, yp = k2+2) with inline x-halo duplicates
    float2* gbase = g_final + ((k2 + 2) * NP + 2) * NCOIL + 2*cp;
    // y-halo duplicate row (wrap +-640 rows), if this k2 is in a halo band
    bool dup = (k2 < 3) || (k2 >= 638);
    long ddelta = (k2 < 3) ? (long)640 * NP * NCOIL : -(long)640 * NP * NCOIL;

    for (int kr = tid; kr < NG; kr += 256) {
        float2 a = SA[0][PHYS(kr)];
        float2 bb = SA[1][PHYS(kr)];
        float4 v4 = make_float4(a.x, a.y, bb.x, bb.y);
        float2* dst = gbase + kr * NCOIL;
        *reinterpret_cast<float4*>(dst) = v4;
        // x-halo: kr<3 -> xp=kr+642 (offset +640 cols); kr>=638 -> xp=kr-638 (offset -640 cols)
        if (kr < 3)    *reinterpret_cast<float4*>(dst + 640 * NCOIL) = v4;
        if (kr >= 638) *reinterpret_cast<float4*>(dst - 640 * NCOIL) = v4;
        if (dup) {
            float2* dst2 = dst + ddelta;
            *reinterpret_cast<float4*>(dst2) = v4;
            if (kr < 3)    *reinterpret_cast<float4*>(dst2 + 640 * NCOIL) = v4;
            if (kr >= 638) *reinterpret_cast<float4*>(dst2 - 640 * NCOIL) = v4;
        }
    }
}

// ---------------- KB interpolation: warp/sample, lane=(coilpair, tapgroup), float4 loads --------
__global__ void interp_kernel(const float* __restrict__ kt, float2* __restrict__ out) {
    int m    = blockIdx.x * 8 + (threadIdx.x >> 5);
    int lane = threadIdx.x & 31;

    const float BETA_F = (float)BETA_D;
    const float G2PI   = 101.85916357881302f;   // 640/(2*pi)
    const unsigned FULL = 0xffffffffu;

    float om1 = __ldg(kt + m);
    float om2 = __ldg(kt + M_SAMP + m);
    float tx = om1 * G2PI; if (tx < 0.f) tx += 640.f;
    float ty = om2 * G2PI; if (ty < 0.f) ty += 640.f;
    float bx = floorf(tx), by = floorf(ty);

    // KB kernel values: lanes 0..5 -> x taps, 6..11 -> y taps
    float kv = 0.f;
    if (lane < 12) {
        bool isx = lane < 6;
        int  sl  = isx ? lane : lane - 6;
        float t  = isx ? tx : ty;
        float bqq= isx ? bx : by;
        float u  = t - (bqq + (float)(sl - 2));
        float mm = fabsf(u) * (1.f/3.f);
        float arg = fmaxf(1.f - mm*mm, 0.f);
        kv = (mm <= 1.f) ? cyl_bessel_i0f(BETA_F * sqrtf(arg)) * (1.f/6.f) : 0.f;
    }

    int cp  = lane >> 2;          // coil pair 0..5 (active lanes < 24)
    int tg  = lane & 3;           // tap group: h = x-half, jh = y-half
    int h   = tg & 1;
    int jh  = tg >> 1;
    bool act = (lane < 24);

    float wxl[3], wyl[3];
    #pragma unroll
    for (int t = 0; t < 3; ++t) wxl[t] = __shfl_sync(FULL, kv, h*3 + t);
    #pragma unroll
    for (int j = 0; j < 3; ++j) wyl[j] = __shfl_sync(FULL, kv, 6 + jh*3 + j);

    // tap (global jj = jh*3+j, tt = h*3+t) at padded cell (byi+jj, bxi+tt), coils 2cp,2cp+1
    int bxi = (int)bx, byi = (int)by;
    const float4* p4 = reinterpret_cast<const float4*>(
        g_final + (((byi + jh*3) * NP) + (bxi + h*3)) * NCOIL) + (act ? cp : 0);

    float re0 = 0.f, im0 = 0.f, re1 = 0.f, im1 = 0.f;
    if (act) {
        #pragma unroll
        for (int j = 0; j < 3; ++j) {
            #pragma unroll
            for (int t = 0; t < 3; ++t) {
                float4 g = __ldg(p4 + (j * NP + t) * (NCOIL/2));
                float w = wxl[t] * wyl[j];
                re0 = fmaf(w, g.x, re0);
                im0 = fmaf(w, g.y, im0);
                re1 = fmaf(w, g.z, re1);
                im1 = fmaf(w, g.w, im1);
            }
        }
    }
    // reduce across the 4 tap-groups of this coil pair
    re0 += __shfl_xor_sync(FULL, re0, 1);  im0 += __shfl_xor_sync(FULL, im0, 1);
    re1 += __shfl_xor_sync(FULL, re1, 1);  im1 += __shfl_xor_sync(FULL, im1, 1);
    re0 += __shfl_xor_sync(FULL, re0, 2);  im0 += __shfl_xor_sync(FULL, im0, 2);
    re1 += __shfl_xor_sync(FULL, re1, 2);  im1 += __shfl_xor_sync(FULL, im1, 2);

    if (act && tg == 0) {
        out[(2*cp)     * M_SAMP + m] = make_float2(re0, im0);
        out[(2*cp + 1) * M_SAMP + m] = make_float2(re1, im1);
    }
}

// ---------------- launch ----------------
extern "C" void kernel_launch(void* const* d_in, const int* in_sizes, int n_in,
                              void* d_out, int out_size) {
    const float* imr = (const float*)d_in[0];
    const float* imi = (const float*)d_in[1];
    const float* smr = (const float*)d_in[2];
    const float* smi = (const float*)d_in[3];
    const float* kt  = (const float*)d_in[4];

    prep_kernel<<<1, 640>>>();
    fftA_kernel<<<NCOIL * 160, 256>>>(imr, imi, smr, smi);   // 1920 CTAs, 2 rows each
    fftB_kernel<<<NG * 6, 256>>>();                          // 3840 CTAs, 2 coils each, halo fused
    interp_kernel<<<M_SAMP / 8, 256>>>(kt, (float2*)d_out);
}